// round 8
// baseline (speedup 1.0000x reference)
#include <cuda_runtime.h>

typedef unsigned int u32;
typedef unsigned long long u64;

#define BATCH  8
#define NPTS   100000
#define NCLS   10
#define KTOP   1000
#define NROWS  (BATCH * NCLS)      // 80
#define NFLAT  (NCLS * KTOP)       // 10000
#define NBINS  65536               // 16-bit digit histogram
#define ORD_NEG1 0x407FFFFFu       // f2ord(-1.0f)
#define TI     512

// ---------------- static device scratch -------------------------------------
__device__ u32    d_ord  [NROWS * NPTS];        // 32 MB ordered score bits
__device__ u32    d_hist [NROWS * NBINS];       // 20 MB per-row 16-bit histograms
__device__ u64    d_k1   [NROWS * KTOP];        // stage-1 sorted keys
__device__ float4 d_corn1[NROWS * KTOP];
__device__ u64    d_k2   [BATCH * NFLAT];
__device__ u64    d_k2s  [BATCH * KTOP];
__device__ float4 d_corn2[BATCH * KTOP];
__device__ float4 d_raw2 [BATCH * KTOP];

// ---------------- helpers ----------------------------------------------------
__device__ __forceinline__ u32 f2ord(float f) {
    u32 b = __float_as_uint(f);
    return b ^ ((b & 0x80000000u) ? 0xFFFFFFFFu : 0x80000000u);
}
__device__ __forceinline__ float ord2f(u32 u) {
    u32 b = u ^ ((u & 0x80000000u) ? 0x80000000u : 0xFFFFFFFFu);
    return __uint_as_float(b);
}

__device__ void bitonic_desc(u64* s, int n) {
    for (int k = 2; k <= n; k <<= 1) {
        for (int j = k >> 1; j > 0; j >>= 1) {
            __syncthreads();
            for (int i = threadIdx.x; i < n; i += blockDim.x) {
                int ixj = i ^ j;
                if (ixj > i) {
                    u64 a = s[i], bb = s[ixj];
                    if ((a < bb) == ((i & k) == 0)) { s[i] = bb; s[ixj] = a; }
                }
            }
        }
    }
    __syncthreads();
}

// Warp-aggregated global histogram add. Fully-converged warps only.
__device__ __forceinline__ void hist_add_g(u32* hist, bool part, u32 idx, int lane) {
    u32 act = __ballot_sync(0xFFFFFFFFu, part);
    if (part) {
        u32 peers = __match_any_sync(act, idx);
        if (lane == __ffs(peers) - 1)
            atomicAdd(&hist[idx], (u32)__popc(peers));
    }
}

// Warp-aggregated shared histogram add. Fully-converged warps only.
__device__ __forceinline__ void hist_add(u32* hist, bool part, u32 dgt, int lane) {
    u32 act = __ballot_sync(0xFFFFFFFFu, part);
    if (part) {
        u32 peers = __match_any_sync(act, dgt);
        if (lane == __ffs(peers) - 1)
            atomicAdd(&hist[dgt], (u32)__popc(peers));
    }
}

// Highest 12-bit bin with count(> bin) < K <= count(>= bin).  1024 threads.
__device__ void select_bin(const u32* hist, u32* swarp, int K, u32* s_sel, int* s_krem) {
    int t = threadIdx.x, lane = t & 31, wid = t >> 5;
    u32 h0 = hist[4 * t], h1 = hist[4 * t + 1], h2 = hist[4 * t + 2], h3 = hist[4 * t + 3];
    u32 mysum = h0 + h1 + h2 + h3;
    u32 v = mysum;
    #pragma unroll
    for (int off = 1; off < 32; off <<= 1) {
        u32 n = __shfl_down_sync(0xFFFFFFFFu, v, off);
        if (lane + off < 32) v += n;
    }
    if (lane == 0) swarp[wid] = v;
    __syncthreads();
    if (t < 32) {
        u32 w = swarp[t];
        #pragma unroll
        for (int off = 1; off < 32; off <<= 1) {
            u32 n = __shfl_down_sync(0xFFFFFFFFu, w, off);
            if (lane + off < 32) w += n;
        }
        swarp[t] = w;
    }
    __syncthreads();
    u32 S_incl = v + ((wid < 31) ? swarp[wid + 1] : 0u);
    u32 above = S_incl - mysum;
    if (above < (u32)K && S_incl >= (u32)K) {
        u32 cum = above;
        u32 hh[4] = { h3, h2, h1, h0 };
        int bb[4] = { 4 * t + 3, 4 * t + 2, 4 * t + 1, 4 * t };
        #pragma unroll
        for (int q = 0; q < 4; q++) {
            if (cum + hh[q] >= (u32)K) { *s_sel = (u32)bb[q]; *s_krem = K - (int)cum; break; }
            cum += hh[q];
        }
    }
    __syncthreads();
}

// ---------------- thread-owns-box blocked greedy NMS -------------------------
struct NmsSh {
    float4 box[1024];
    float  area[1024];
    u64    mat[64];
    u32    cand[2];
    u64    alive;
};

__device__ bool nms_greedy(NmsSh* ns, float4 my, float myarea, bool myvalid,
                           float thresh, int tid) {
    bool supp = false, kept = false;
    int myblk = tid >> 6;
    int lane = tid & 31;
    for (int blk = 0; blk < 16; blk++) {
        if ((tid >> 6) == blk) {                 // warp-uniform (2 warps)
            u32 bal = __ballot_sync(0xFFFFFFFFu, myvalid && !supp);
            if (lane == 0) ns->cand[(tid >> 5) & 1] = bal;
        }
        __syncthreads();
        u64 cand = ((u64)ns->cand[1] << 32) | (u64)ns->cand[0];
        int base = blk << 6;

        {   // intra-block 64x64 (4 j's/thread, shfl-OR reduce)
            int i = tid >> 4;
            u64 bits = 0ULL;
            if ((cand >> i) & 1ULL) {
                float4 a = ns->box[base + i];
                float areaA = ns->area[base + i];
                int j0 = (tid & 15) << 2;
                #pragma unroll
                for (int q = 0; q < 4; q++) {
                    int j = j0 + q;
                    if (j > i) {
                        float4 c = ns->box[base + j];
                        float ih = fmaxf(fminf(a.z, c.z) - fmaxf(a.x, c.x), 0.0f);
                        float iw = fmaxf(fminf(a.w, c.w) - fmaxf(a.y, c.y), 0.0f);
                        float inter = ih * iw;
                        float uni = fmaxf(areaA + ns->area[base + j] - inter, 1e-8f);
                        if (inter / uni > thresh) bits |= 1ULL << j;
                    }
                }
            }
            #pragma unroll
            for (int off = 8; off; off >>= 1)
                bits |= __shfl_xor_sync(0xFFFFFFFFu, bits, off);
            if ((tid & 15) == 0) ns->mat[tid >> 4] = bits;
        }
        __syncthreads();

        if (tid == 0) {                          // serial resolve
            u64 suppB = 0ULL, aliveB = 0ULL;
            for (int q0 = 0; q0 < 64; q0 += 8) {
                u64 dw[8];
                #pragma unroll
                for (int r = 0; r < 8; r++) dw[r] = ns->mat[q0 + r];
                #pragma unroll
                for (int r = 0; r < 8; r++) {
                    int q = q0 + r;
                    if (((cand >> q) & 1ULL) && !((suppB >> q) & 1ULL)) {
                        aliveB |= 1ULL << q;
                        suppB |= dw[r];
                    }
                }
            }
            ns->alive = aliveB;
        }
        __syncthreads();
        u64 aliveM = ns->alive;

        if (myblk == blk) {
            kept = myvalid && ((aliveM >> (tid & 63)) & 1ULL);
            supp = !kept;
        } else if (myblk > blk && myvalid && !supp) {
            u64 tmp = aliveM;
            while (tmp) {
                int ii = __ffsll(tmp) - 1;
                tmp &= tmp - 1;
                float4 a = ns->box[base + ii];
                float areaA = ns->area[base + ii];
                float ih = fmaxf(fminf(a.z, my.z) - fmaxf(a.x, my.x), 0.0f);
                float iw = fmaxf(fminf(a.w, my.w) - fmaxf(a.y, my.y), 0.0f);
                float inter = ih * iw;
                float uni = fmaxf(areaA + myarea - inter, 1e-8f);
                if (inter / uni > thresh) { supp = true; break; }
            }
        }
    }
    return kept;
}

// ---------------- K0: zero the histograms ------------------------------------
__global__ void k_zero() {
    uint4* p = (uint4*)d_hist;
    size_t n4 = (size_t)NROWS * NBINS / 4;
    uint4 z = make_uint4(0u, 0u, 0u, 0u);
    for (size_t i = blockIdx.x * (size_t)blockDim.x + threadIdx.x;
         i < n4; i += (size_t)gridDim.x * blockDim.x)
        p[i] = z;
}

// ---------------- K1: mask + transpose + fused 16-bit histogram --------------
__global__ void k_transpose(const float* __restrict__ cls) {
    __shared__ u32 tile[TI * NCLS];
    int b  = blockIdx.y;
    int i0 = blockIdx.x * TI;
    int cnt = min(TI, NPTS - i0);
    int tot = cnt * NCLS;
    int tid = threadIdx.x, bd = blockDim.x, lane = tid & 31;
    const float* src = cls + ((size_t)b * NPTS + i0) * NCLS;
    int nit = (tot + bd - 1) / bd;
    for (int it = 0; it < nit; it++) {         // uniform trips for collectives
        int t = it * bd + tid;
        bool inr = (t < tot);
        u32 u = 0u, idx = 0u;
        if (inr) {
            float s = src[t];
            s = (s >= 0.05f) ? s : -1.0f;
            u = f2ord(s);
            tile[t] = u;
            int c = t % NCLS;
            idx = (u32)(b * NCLS + c) * (u32)NBINS + (u >> 16);
        }
        hist_add_g(d_hist, inr, idx, lane);
    }
    __syncthreads();
    for (int c = 0; c < NCLS; ++c) {
        u32* dst = d_ord + (size_t)(b * NCLS + c) * NPTS + i0;
        for (int r = tid; r < cnt; r += bd)
            dst[r] = tile[r * NCLS + c];
    }
}

// ---------------- K2: stage-1 threshold-from-hist + single collect sweep -----
__global__ void __launch_bounds__(1024) k_sel1(const float4* __restrict__ boxes) {
    __shared__ u32 swarp[32];
    __shared__ u64 sbig[1024], stie[1024], sfin[1024];
    __shared__ u32 s_sel;
    __shared__ int s_krem, s_ng, s_nt;

    int row = blockIdx.x;
    int b = row / NCLS, c = row % NCLS;
    const u32* ord = d_ord + (size_t)row * NPTS;
    const u32* hist = d_hist + (size_t)row * NBINS;
    int tid = threadIdx.x, lane = tid & 31, wid = tid >> 5;

    if (tid == 0) { s_ng = 0; s_nt = 0; }

    // ---- threshold: each thread owns 64 bins [64*tid, 64*tid+64)
    u32 mysum = 0;
    {
        const uint4* h4 = (const uint4*)(hist + tid * 64);
        #pragma unroll
        for (int q = 0; q < 16; q++) {
            uint4 v = h4[q];
            mysum += v.x + v.y + v.z + v.w;
        }
    }
    u32 v = mysum;
    #pragma unroll
    for (int off = 1; off < 32; off <<= 1) {
        u32 n = __shfl_down_sync(0xFFFFFFFFu, v, off);
        if (lane + off < 32) v += n;
    }
    if (lane == 0) swarp[wid] = v;
    __syncthreads();
    if (tid < 32) {
        u32 w = swarp[tid];
        #pragma unroll
        for (int off = 1; off < 32; off <<= 1) {
            u32 n = __shfl_down_sync(0xFFFFFFFFu, w, off);
            if (lane + off < 32) w += n;
        }
        swarp[tid] = w;
    }
    __syncthreads();
    u32 S_incl = v + ((wid < 31) ? swarp[wid + 1] : 0u);
    u32 above = S_incl - mysum;
    if (above < (u32)KTOP && S_incl >= (u32)KTOP) {
        u32 cum = above;
        for (int q = 63; q >= 0; q--) {           // walk own bins high -> low
            u32 hh = hist[tid * 64 + q];
            if (cum + hh >= (u32)KTOP) { s_sel = (u32)(tid * 64 + q); s_krem = KTOP - (int)cum; break; }
            cum += hh;
        }
    }
    __syncthreads();
    u32 T16 = s_sel;
    int krem = s_krem;

    // ---- single collect sweep (no warp collectives inside)
    for (int i = tid; i < NPTS; i += 1024) {
        u32 u = ord[i];
        u32 p16 = u >> 16;
        if (p16 > T16) {
            int pos = atomicAdd(&s_ng, 1);
            if (pos < 1024) sbig[pos] = ((u64)u << 32) | (u32)(~i);
        } else if (p16 == T16) {
            int pos = atomicAdd(&s_nt, 1);
            if (pos < 1024) stie[pos] = ((u64)u << 32) | (u32)(~i);
        }
    }
    __syncthreads();
    int ng = min(s_ng, 1024), nt = min(s_nt, 1024);
    int take = min(krem, nt);
    for (int t = tid; t < 1024; t += 1024) if (t >= nt) stie[t] = 0ULL;
    bitonic_desc(stie, 1024);
    for (int t = tid; t < 1024; t += 1024) {
        u64 vv = 0ULL;
        if (t < ng) vv = sbig[t];
        else if (t < ng + take) vv = stie[t - ng];
        sfin[t] = vv;
    }
    bitonic_desc(sfin, 1024);

    if (tid < KTOP) {
        u64 key = sfin[tid];
        d_k1[row * KTOP + tid] = key;
        u32 hi = (u32)(key >> 32);
        float s = ord2f(hi);
        bool valid = (s >= 0.05f);
        u32 idx = ~(u32)key;
        if (!valid || idx >= NPTS) idx = 0;
        float4 bb = boxes[(size_t)b * NPTS + idx];
        d_corn1[row * KTOP + tid] = make_float4(bb.y - 0.5f * bb.w, bb.x - 0.5f * bb.z,
                                                bb.y + 0.5f * bb.w, bb.x + 0.5f * bb.z);
    }
}

// ---------------- K3: stage-1 NMS + stage-2 key emission ---------------------
__global__ void __launch_bounds__(1024) k_nms1() {
    __shared__ NmsSh ns;
    int row = blockIdx.x, tid = threadIdx.x;
    int b = row / NCLS, c = row % NCLS;
    u64 mykey = 0ULL;
    bool myvalid = false;
    float4 my = make_float4(0.f, 0.f, 0.f, 0.f);
    if (tid < KTOP) {
        mykey = d_k1[row * KTOP + tid];
        myvalid = ord2f((u32)(mykey >> 32)) >= 0.05f;
        my = d_corn1[(size_t)row * KTOP + tid];
    }
    float myarea = (my.z - my.x) * (my.w - my.y);
    ns.box[tid] = my;
    ns.area[tid] = myarea;
    __syncthreads();

    bool kept = nms_greedy(&ns, my, myarea, myvalid, 0.4f, tid);

    if (tid < KTOP) {
        u32 hi = kept ? (u32)(mykey >> 32) : ORD_NEG1;
        u32 flat = (u32)(c * KTOP + tid);
        d_k2[b * NFLAT + flat] = ((u64)hi << 32) | (u32)(~flat);
    }
}

// ---------------- K4: stage-2 select (5x12-bit radix on u64) + gather --------
__global__ void __launch_bounds__(1024) k_sel2(const float4* __restrict__ boxes) {
    __shared__ u32 hist[4096];
    __shared__ u32 swarp[32];
    __shared__ u64 sbig[1024], stie[256], sfin[1024];
    __shared__ u32 s_sel;
    __shared__ int s_krem, s_ng, s_nt;

    int b = blockIdx.x, tid = threadIdx.x, lane = tid & 31;
    const u64* keys = d_k2 + b * NFLAT;
    if (tid == 0) { s_ng = 0; s_nt = 0; }

    const int nIt2 = (NFLAT + 1023) / 1024;
    u64 prefix = 0ULL;
    int Kc = KTOP;
    for (int p = 0; p < 5; p++) {
        int shift = 52 - 12 * p;
        for (int t = tid; t < 4096; t += 1024) hist[t] = 0u;
        __syncthreads();
        for (int it = 0; it < nIt2; it++) {
            int f = it * 1024 + tid;
            bool inr = (f < NFLAT);
            u64 k = inr ? keys[f] : 0ULL;
            bool part = inr && ((p == 0) || ((k >> (shift + 12)) == prefix));
            hist_add(hist, part, (u32)((k >> shift) & 4095ULL), lane);
        }
        __syncthreads();
        select_bin(hist, swarp, Kc, &s_sel, &s_krem);
        prefix = (prefix << 12) | (u64)s_sel;
        Kc = s_krem;
    }

    for (int f = tid; f < NFLAT; f += 1024) {
        u64 k = keys[f];
        u64 p60 = k >> 4;
        if (p60 > prefix) {
            int pos = atomicAdd(&s_ng, 1);
            if (pos < 1024) sbig[pos] = k;
        } else if (p60 == prefix) {
            int pos = atomicAdd(&s_nt, 1);
            if (pos < 256) stie[pos] = k;
        }
    }
    __syncthreads();
    int ng = min(s_ng, 1024), nt = min(s_nt, 256);
    int take = min(Kc, nt);
    for (int t = tid; t < 256; t += 1024) if (t >= nt) stie[t] = 0ULL;
    bitonic_desc(stie, 256);
    for (int t = tid; t < 1024; t += 1024) {
        u64 vv = 0ULL;
        if (t < ng) vv = sbig[t];
        else if (t < ng + take) vv = stie[t - ng];
        sfin[t] = vv;
    }
    bitonic_desc(sfin, 1024);

    if (tid < KTOP) {
        u64 key = sfin[tid];
        d_k2s[b * KTOP + tid] = key;
        u32 hi = (u32)(key >> 32);
        float s = ord2f(hi);
        bool valid = (s >= 0.05f);
        u32 flat = ~(u32)key;
        u32 orig = 0;
        if (valid && flat < NFLAT) {
            int cc2 = (int)(flat / KTOP);
            u32 kk = flat % KTOP;
            orig = ~(u32)d_k1[(b * NCLS + cc2) * KTOP + kk];
            if (orig >= NPTS) orig = 0;
        } else valid = false;
        float4 bb = boxes[(size_t)b * NPTS + orig];
        d_raw2[b * KTOP + tid] = bb;
        d_corn2[b * KTOP + tid] = make_float4(bb.y - 0.5f * bb.w, bb.x - 0.5f * bb.z,
                                              bb.y + 0.5f * bb.w, bb.x + 0.5f * bb.z);
    }
}

// ---------------- K5: stage-2 NMS + compaction + output ----------------------
__global__ void __launch_bounds__(1024) k_nms2(float* __restrict__ out) {
    __shared__ NmsSh ns;
    __shared__ int swarp2[32];
    int b = blockIdx.x, tid = threadIdx.x;
    int lane = tid & 31, wid = tid >> 5;

    u64 mykey = 0ULL;
    bool myvalid = false;
    float4 my = make_float4(0.f, 0.f, 0.f, 0.f);
    if (tid < KTOP) {
        mykey = d_k2s[b * KTOP + tid];
        myvalid = ord2f((u32)(mykey >> 32)) >= 0.05f;
        my = d_corn2[(size_t)b * KTOP + tid];
    }
    float myarea = (my.z - my.x) * (my.w - my.y);
    ns.box[tid] = my;
    ns.area[tid] = myarea;
    __syncthreads();

    bool kept = nms_greedy(&ns, my, myarea, myvalid, 0.65f, tid);

    int flag = kept ? 1 : 0;
    int v = flag;
    #pragma unroll
    for (int off = 1; off < 32; off <<= 1) {
        int n = __shfl_up_sync(0xFFFFFFFFu, v, off);
        if (lane >= off) v += n;
    }
    if (lane == 31) swarp2[wid] = v;
    __syncthreads();
    if (tid < 32) {
        int w = swarp2[tid];
        #pragma unroll
        for (int off = 1; off < 32; off <<= 1) {
            int n = __shfl_up_sync(0xFFFFFFFFu, w, off);
            if (lane >= off) w += n;
        }
        swarp2[tid] = w;
    }
    __syncthreads();
    int incl = v + (wid ? swarp2[wid - 1] : 0);
    int total = swarp2[31];

    if (flag) {
        int m = incl - 1;
        float conf = ord2f((u32)(mykey >> 32));
        u32 flat = ~(u32)mykey;
        int cls = (int)(flat / KTOP);
        float4 raw = d_raw2[b * KTOP + tid];
        float* o = out + ((size_t)b * KTOP + m) * 6;
        o[0] = raw.x; o[1] = raw.y; o[2] = raw.z; o[3] = raw.w;
        o[4] = (float)cls; o[5] = conf;
    }
    for (int m = total + tid; m < KTOP; m += 1024) {
        float* o = out + ((size_t)b * KTOP + m) * 6;
        #pragma unroll
        for (int q = 0; q < 6; ++q) o[q] = 0.f;
    }
}

// ---------------- launch ------------------------------------------------------
extern "C" void kernel_launch(void* const* d_in, const int* in_sizes, int n_in,
                              void* d_out, int out_size) {
    const float*  cls   = (const float*)d_in[0];
    const float4* boxes = (const float4*)d_in[1];
    float* out = (float*)d_out;

    k_zero<<<2048, 256>>>();
    k_transpose<<<dim3((NPTS + TI - 1) / TI, BATCH), 512>>>(cls);
    k_sel1<<<NROWS, 1024>>>(boxes);
    k_nms1<<<NROWS, 1024>>>();
    k_sel2<<<BATCH, 1024>>>(boxes);
    k_nms2<<<BATCH, 1024>>>(out);
}

// round 9
// speedup vs baseline: 1.0675x; 1.0675x over previous
#include <cuda_runtime.h>

typedef unsigned int u32;
typedef unsigned long long u64;

#define BATCH  8
#define NPTS   100000
#define NCLS   10
#define KTOP   1000
#define NROWS  (BATCH * NCLS)      // 80
#define NFLAT  (NCLS * KTOP)      // 10000
#define ORD_NEG1 0x407FFFFFu       // f2ord(-1.0f)
#define TI     512

// dynamic smem layout for k_s1/k_s2 (phase A select, phase B NMS overlays it)
#define OFF_HIST 0                 // u32[4096]  16384
#define OFF_BIG  16384             // u64[1024]   8192
#define OFF_TIE  24576             // u64[256]    2048
#define OFF_FIN  26624             // u64[1024]   8192
#define SMEM_SZ  34816

// ---------------- static device scratch -------------------------------------
__device__ u32 d_ord[NROWS * NPTS];       // 32 MB ordered score bits
__device__ u64 d_k1 [NROWS * KTOP];       // stage-1 sorted keys (sel2 needs them)
__device__ u64 d_k2 [BATCH * NFLAT];      // stage-2 candidate keys

// ---------------- helpers ----------------------------------------------------
__device__ __forceinline__ u32 f2ord(float f) {
    u32 b = __float_as_uint(f);
    return b ^ ((b & 0x80000000u) ? 0xFFFFFFFFu : 0x80000000u);
}
__device__ __forceinline__ float ord2f(u32 u) {
    u32 b = u ^ ((u & 0x80000000u) ? 0x80000000u : 0xFFFFFFFFu);
    return __uint_as_float(b);
}

// Decision identical to RN(inter/uni) > t: margins (+-1e-3 relative) dwarf the
// 2^-24 division rounding, so the exact RN divide only runs in the rare band.
__device__ __forceinline__ bool iou_gt(float4 a, float areaA, float4 c, float areaC,
                                       float t, float tLo, float tHi) {
    float ih = fmaxf(fminf(a.z, c.z) - fmaxf(a.x, c.x), 0.0f);
    float iw = fmaxf(fminf(a.w, c.w) - fmaxf(a.y, c.y), 0.0f);
    float inter = ih * iw;
    float uni = fmaxf(areaA + areaC - inter, 1e-8f);
    if (inter > tHi * uni) return true;
    if (inter >= tLo * uni) return inter / uni > t;   // rare exact band
    return false;
}

__device__ void bitonic_desc(u64* s, int n) {
    for (int k = 2; k <= n; k <<= 1) {
        for (int j = k >> 1; j > 0; j >>= 1) {
            __syncthreads();
            for (int i = threadIdx.x; i < n; i += blockDim.x) {
                int ixj = i ^ j;
                if (ixj > i) {
                    u64 a = s[i], bb = s[ixj];
                    if ((a < bb) == ((i & k) == 0)) { s[i] = bb; s[ixj] = a; }
                }
            }
        }
    }
    __syncthreads();
}

// Warp-aggregated shared histogram add. Fully-converged warps only.
__device__ __forceinline__ void hist_add(u32* hist, bool part, u32 dgt, int lane) {
    u32 act = __ballot_sync(0xFFFFFFFFu, part);
    if (part) {
        u32 peers = __match_any_sync(act, dgt);
        if (lane == __ffs(peers) - 1)
            atomicAdd(&hist[dgt], (u32)__popc(peers));
    }
}

// Highest 12-bit bin with count(> bin) < K <= count(>= bin).  1024 threads.
__device__ void select_bin(const u32* hist, u32* swarp, int K, u32* s_sel, int* s_krem) {
    int t = threadIdx.x, lane = t & 31, wid = t >> 5;
    u32 h0 = hist[4 * t], h1 = hist[4 * t + 1], h2 = hist[4 * t + 2], h3 = hist[4 * t + 3];
    u32 mysum = h0 + h1 + h2 + h3;
    u32 v = mysum;
    #pragma unroll
    for (int off = 1; off < 32; off <<= 1) {
        u32 n = __shfl_down_sync(0xFFFFFFFFu, v, off);
        if (lane + off < 32) v += n;
    }
    if (lane == 0) swarp[wid] = v;
    __syncthreads();
    if (t < 32) {
        u32 w = swarp[t];
        #pragma unroll
        for (int off = 1; off < 32; off <<= 1) {
            u32 n = __shfl_down_sync(0xFFFFFFFFu, w, off);
            if (lane + off < 32) w += n;
        }
        swarp[t] = w;
    }
    __syncthreads();
    u32 S_incl = v + ((wid < 31) ? swarp[wid + 1] : 0u);
    u32 above = S_incl - mysum;
    if (above < (u32)K && S_incl >= (u32)K) {
        u32 cum = above;
        u32 hh[4] = { h3, h2, h1, h0 };
        int bb[4] = { 4 * t + 3, 4 * t + 2, 4 * t + 1, 4 * t };
        #pragma unroll
        for (int q = 0; q < 4; q++) {
            if (cum + hh[q] >= (u32)K) { *s_sel = (u32)bb[q]; *s_krem = K - (int)cum; break; }
            cum += hh[q];
        }
    }
    __syncthreads();
}

// ---------------- thread-owns-box blocked greedy NMS -------------------------
struct NmsSh {
    float4 box[1024];
    float  area[1024];
    u64    mat[64];
    u32    cand[2];
    u64    alive;
};

__device__ bool nms_greedy(NmsSh* ns, float4 my, float myarea, bool myvalid,
                           float thresh, int tid) {
    const float tLo = thresh * 0.999f, tHi = thresh * 1.001f;
    bool supp = false, kept = false;
    int myblk = tid >> 6;
    int lane = tid & 31;
    for (int blk = 0; blk < 16; blk++) {
        if ((tid >> 6) == blk) {                 // warp-uniform (2 warps)
            u32 bal = __ballot_sync(0xFFFFFFFFu, myvalid && !supp);
            if (lane == 0) ns->cand[(tid >> 5) & 1] = bal;
        }
        __syncthreads();
        u64 cand = ((u64)ns->cand[1] << 32) | (u64)ns->cand[0];
        int base = blk << 6;

        {   // intra-block 64x64 over candidate pairs only
            int i = tid >> 4;
            u64 bits = 0ULL;
            if ((cand >> i) & 1ULL) {
                float4 a = ns->box[base + i];
                float areaA = ns->area[base + i];
                int j0 = (tid & 15) << 2;
                #pragma unroll
                for (int q = 0; q < 4; q++) {
                    int j = j0 + q;
                    if (j > i && ((cand >> j) & 1ULL)) {
                        if (iou_gt(a, areaA, ns->box[base + j], ns->area[base + j],
                                   thresh, tLo, tHi))
                            bits |= 1ULL << j;
                    }
                }
            }
            #pragma unroll
            for (int off = 8; off; off >>= 1)
                bits |= __shfl_xor_sync(0xFFFFFFFFu, bits, off);
            if ((tid & 15) == 0) ns->mat[tid >> 4] = bits;
        }
        __syncthreads();

        if (tid == 0) {                          // serial resolve
            u64 suppB = 0ULL, aliveB = 0ULL;
            for (int q0 = 0; q0 < 64; q0 += 8) {
                u64 dw[8];
                #pragma unroll
                for (int r = 0; r < 8; r++) dw[r] = ns->mat[q0 + r];
                #pragma unroll
                for (int r = 0; r < 8; r++) {
                    int q = q0 + r;
                    if (((cand >> q) & 1ULL) && !((suppB >> q) & 1ULL)) {
                        aliveB |= 1ULL << q;
                        suppB |= dw[r];
                    }
                }
            }
            ns->alive = aliveB;
        }
        __syncthreads();
        u64 aliveM = ns->alive;

        if (myblk == blk) {
            kept = myvalid && ((aliveM >> (tid & 63)) & 1ULL);
            supp = !kept;
        } else if (myblk > blk && myvalid && !supp) {
            u64 tmp = aliveM;
            while (tmp) {
                int ii = __ffsll(tmp) - 1;
                tmp &= tmp - 1;
                if (iou_gt(ns->box[base + ii], ns->area[base + ii], my, myarea,
                           thresh, tLo, tHi)) { supp = true; break; }
            }
        }
    }
    return kept;
}

// ---------------- K1: mask + transpose to per-(b,c) rows --------------------
__global__ void k_transpose(const float* __restrict__ cls) {
    __shared__ u32 tile[TI * NCLS];
    int b  = blockIdx.y;
    int i0 = blockIdx.x * TI;
    int cnt = min(TI, NPTS - i0);
    const float* src = cls + ((size_t)b * NPTS + i0) * NCLS;
    for (int t = threadIdx.x; t < cnt * NCLS; t += blockDim.x) {
        float s = src[t];
        s = (s >= 0.05f) ? s : -1.0f;
        tile[t] = f2ord(s);
    }
    __syncthreads();
    for (int c = 0; c < NCLS; ++c) {
        u32* dst = d_ord + (size_t)(b * NCLS + c) * NPTS + i0;
        for (int r = threadIdx.x; r < cnt; r += blockDim.x)
            dst[r] = tile[r * NCLS + c];
    }
}

// ---------------- K2: fused stage-1 select + NMS -----------------------------
__global__ void __launch_bounds__(1024) k_s1(const float4* __restrict__ boxes) {
    extern __shared__ char sm[];
    u32* hist = (u32*)(sm + OFF_HIST);
    u64* sbig = (u64*)(sm + OFF_BIG);
    u64* stie = (u64*)(sm + OFF_TIE);
    u64* sfin = (u64*)(sm + OFF_FIN);
    NmsSh* ns = (NmsSh*)sm;
    __shared__ u32 swarp[32];
    __shared__ u32 s_sel;
    __shared__ int s_krem, s_ng, s_nt;

    int row = blockIdx.x;
    int b = row / NCLS, c = row % NCLS;
    const u32* ord = d_ord + (size_t)row * NPTS;
    int tid = threadIdx.x, lane = tid & 31;
    const int nIter = (NPTS + 1023) / 1024;

    if (tid == 0) { s_ng = 0; s_nt = 0; }
    for (int t = tid; t < 4096; t += 1024) hist[t] = 0u;
    __syncthreads();

    // pass A: digit = bits 31..20
    for (int it = 0; it < nIter; it++) {
        int i = it * 1024 + tid;
        bool inr = (i < NPTS);
        u32 u = inr ? ord[i] : 0u;
        hist_add(hist, inr, u >> 20, lane);
    }
    __syncthreads();
    select_bin(hist, swarp, KTOP, &s_sel, &s_krem);
    u32 D1 = s_sel;
    int K2v = s_krem;

    // pass B: digit = bits 19..8 among prefix matches
    for (int t = tid; t < 4096; t += 1024) hist[t] = 0u;
    __syncthreads();
    for (int it = 0; it < nIter; it++) {
        int i = it * 1024 + tid;
        bool inr = (i < NPTS);
        u32 u = inr ? ord[i] : 0u;
        bool part = inr && ((u >> 20) == D1);
        hist_add(hist, part, (u >> 8) & 4095u, lane);
    }
    __syncthreads();
    select_bin(hist, swarp, K2v, &s_sel, &s_krem);
    u32 T24 = (D1 << 12) | s_sel;
    int krem = s_krem;

    // collect (no warp collectives inside)
    for (int i = tid; i < NPTS; i += 1024) {
        u32 u = ord[i];
        u32 p24 = u >> 8;
        if (p24 > T24) {
            int pos = atomicAdd(&s_ng, 1);
            if (pos < 1024) sbig[pos] = ((u64)u << 32) | (u32)(~i);
        } else if (p24 == T24) {
            int pos = atomicAdd(&s_nt, 1);
            if (pos < 256) stie[pos] = ((u64)u << 32) | (u32)(~i);
        }
    }
    __syncthreads();
    int ng = min(s_ng, 1024), nt = min(s_nt, 256);
    int take = min(krem, nt);
    for (int t = tid; t < 256; t += 1024) if (t >= nt) stie[t] = 0ULL;
    bitonic_desc(stie, 256);
    for (int t = tid; t < 1024; t += 1024) {
        u64 v = 0ULL;
        if (t < ng) v = sbig[t];
        else if (t < ng + take) v = stie[t - ng];
        sfin[t] = v;
    }
    bitonic_desc(sfin, 1024);

    // handoff: keys + corners to registers, then overlay smem with NmsSh
    u64 mykey = 0ULL;
    bool myvalid = false;
    float4 my = make_float4(0.f, 0.f, 0.f, 0.f);
    if (tid < KTOP) {
        mykey = sfin[tid];
        d_k1[row * KTOP + tid] = mykey;
        u32 hi = (u32)(mykey >> 32);
        float s = ord2f(hi);
        myvalid = (s >= 0.05f);
        u32 idx = ~(u32)mykey;
        if (!myvalid || idx >= NPTS) idx = 0;
        float4 bb = boxes[(size_t)b * NPTS + idx];
        my = make_float4(bb.y - 0.5f * bb.w, bb.x - 0.5f * bb.z,
                         bb.y + 0.5f * bb.w, bb.x + 0.5f * bb.z);
    }
    __syncthreads();          // everyone done with sfin region before overlay? (sfin untouched by NmsSh, but order writes)
    float myarea = (my.z - my.x) * (my.w - my.y);
    ns->box[tid] = my;
    ns->area[tid] = myarea;
    __syncthreads();

    bool kept = nms_greedy(ns, my, myarea, myvalid, 0.4f, tid);

    if (tid < KTOP) {
        u32 hi = kept ? (u32)(mykey >> 32) : ORD_NEG1;
        u32 flat = (u32)(c * KTOP + tid);
        d_k2[b * NFLAT + flat] = ((u64)hi << 32) | (u32)(~flat);
    }
}

// ---------------- K3: fused stage-2 select + NMS + output --------------------
__global__ void __launch_bounds__(1024) k_s2(const float4* __restrict__ boxes,
                                             float* __restrict__ out) {
    extern __shared__ char sm[];
    u32* hist = (u32*)(sm + OFF_HIST);
    u64* sbig = (u64*)(sm + OFF_BIG);
    u64* stie = (u64*)(sm + OFF_TIE);
    u64* sfin = (u64*)(sm + OFF_FIN);
    NmsSh* ns = (NmsSh*)sm;
    __shared__ u32 swarp[32];
    __shared__ int swarp2[32];
    __shared__ u32 s_sel;
    __shared__ int s_krem, s_ng, s_nt;

    int b = blockIdx.x, tid = threadIdx.x, lane = tid & 31, wid = tid >> 5;
    const u64* keys = d_k2 + b * NFLAT;
    if (tid == 0) { s_ng = 0; s_nt = 0; }

    const int nIt2 = (NFLAT + 1023) / 1024;
    u64 prefix = 0ULL;
    int Kc = KTOP;
    for (int p = 0; p < 5; p++) {
        int shift = 52 - 12 * p;
        for (int t = tid; t < 4096; t += 1024) hist[t] = 0u;
        __syncthreads();
        for (int it = 0; it < nIt2; it++) {
            int f = it * 1024 + tid;
            bool inr = (f < NFLAT);
            u64 k = inr ? keys[f] : 0ULL;
            bool part = inr && ((p == 0) || ((k >> (shift + 12)) == prefix));
            hist_add(hist, part, (u32)((k >> shift) & 4095ULL), lane);
        }
        __syncthreads();
        select_bin(hist, swarp, Kc, &s_sel, &s_krem);
        prefix = (prefix << 12) | (u64)s_sel;
        Kc = s_krem;
    }

    for (int f = tid; f < NFLAT; f += 1024) {
        u64 k = keys[f];
        u64 p60 = k >> 4;
        if (p60 > prefix) {
            int pos = atomicAdd(&s_ng, 1);
            if (pos < 1024) sbig[pos] = k;
        } else if (p60 == prefix) {
            int pos = atomicAdd(&s_nt, 1);
            if (pos < 256) stie[pos] = k;
        }
    }
    __syncthreads();
    int ng = min(s_ng, 1024), nt = min(s_nt, 256);
    int take = min(Kc, nt);
    for (int t = tid; t < 256; t += 1024) if (t >= nt) stie[t] = 0ULL;
    bitonic_desc(stie, 256);
    for (int t = tid; t < 1024; t += 1024) {
        u64 vv = 0ULL;
        if (t < ng) vv = sbig[t];
        else if (t < ng + take) vv = stie[t - ng];
        sfin[t] = vv;
    }
    bitonic_desc(sfin, 1024);

    // handoff to registers
    u64 mykey = 0ULL;
    bool myvalid = false;
    float4 my = make_float4(0.f, 0.f, 0.f, 0.f);
    float4 myraw = make_float4(0.f, 0.f, 0.f, 0.f);
    if (tid < KTOP) {
        mykey = sfin[tid];
        u32 hi = (u32)(mykey >> 32);
        float s = ord2f(hi);
        myvalid = (s >= 0.05f);
        u32 flat = ~(u32)mykey;
        u32 orig = 0;
        if (myvalid && flat < NFLAT) {
            int cc2 = (int)(flat / KTOP);
            u32 kk = flat % KTOP;
            orig = ~(u32)d_k1[(b * NCLS + cc2) * KTOP + kk];
            if (orig >= NPTS) orig = 0;
        } else myvalid = false;
        float4 bb = boxes[(size_t)b * NPTS + orig];
        myraw = bb;
        my = make_float4(bb.y - 0.5f * bb.w, bb.x - 0.5f * bb.z,
                         bb.y + 0.5f * bb.w, bb.x + 0.5f * bb.z);
    }
    __syncthreads();
    float myarea = (my.z - my.x) * (my.w - my.y);
    ns->box[tid] = my;
    ns->area[tid] = myarea;
    __syncthreads();

    bool kept = nms_greedy(ns, my, myarea, myvalid, 0.65f, tid);

    // stable compaction (= argsort(!keep)) via 2-barrier warp scan
    int flag = kept ? 1 : 0;
    int v = flag;
    #pragma unroll
    for (int off = 1; off < 32; off <<= 1) {
        int n = __shfl_up_sync(0xFFFFFFFFu, v, off);
        if (lane >= off) v += n;
    }
    if (lane == 31) swarp2[wid] = v;
    __syncthreads();
    if (tid < 32) {
        int w = swarp2[tid];
        #pragma unroll
        for (int off = 1; off < 32; off <<= 1) {
            int n = __shfl_up_sync(0xFFFFFFFFu, w, off);
            if (lane >= off) w += n;
        }
        swarp2[tid] = w;
    }
    __syncthreads();
    int incl = v + (wid ? swarp2[wid - 1] : 0);
    int total = swarp2[31];

    if (flag) {
        int m = incl - 1;
        float conf = ord2f((u32)(mykey >> 32));
        u32 flat = ~(u32)mykey;
        int cls = (int)(flat / KTOP);
        float* o = out + ((size_t)b * KTOP + m) * 6;
        o[0] = myraw.x; o[1] = myraw.y; o[2] = myraw.z; o[3] = myraw.w;
        o[4] = (float)cls; o[5] = conf;
    }
    for (int m = total + tid; m < KTOP; m += 1024) {
        float* o = out + ((size_t)b * KTOP + m) * 6;
        #pragma unroll
        for (int q = 0; q < 6; ++q) o[q] = 0.f;
    }
}

// ---------------- launch ------------------------------------------------------
extern "C" void kernel_launch(void* const* d_in, const int* in_sizes, int n_in,
                              void* d_out, int out_size) {
    const float*  cls   = (const float*)d_in[0];
    const float4* boxes = (const float4*)d_in[1];
    float* out = (float*)d_out;

    k_transpose<<<dim3((NPTS + TI - 1) / TI, BATCH), 512>>>(cls);
    k_s1<<<NROWS, 1024, SMEM_SZ>>>(boxes);
    k_s2<<<BATCH, 1024, SMEM_SZ>>>(boxes, out);
}